// round 2
// baseline (speedup 1.0000x reference)
#include <cuda_runtime.h>
#include <math.h>

#define D_MODEL 1024
#define D_FF    4096
#define BATCH   4
#define SEQ     2048
#define ROWS    (BATCH * SEQ)   // 8192
#define EPS     1e-5f

// ---------------- scratch (device globals; no allocations allowed) ----------------
__device__ float g_Q   [(size_t)ROWS * D_MODEL];
__device__ float g_K   [(size_t)ROWS * D_MODEL];
__device__ float g_V   [(size_t)ROWS * D_MODEL];
__device__ float g_S   [(size_t)BATCH * SEQ * SEQ];
__device__ float g_att [(size_t)ROWS * D_MODEL];
__device__ float g_y1  [(size_t)ROWS * D_MODEL];
__device__ float g_y2  [(size_t)ROWS * D_MODEL];
__device__ float g_h   [(size_t)ROWS * D_FF];

// ---------------- reductions ----------------
__device__ __forceinline__ float warp_sum(float v) {
    #pragma unroll
    for (int o = 16; o > 0; o >>= 1) v += __shfl_xor_sync(0xFFFFFFFFu, v, o);
    return v;
}
__device__ __forceinline__ float warp_max(float v) {
    #pragma unroll
    for (int o = 16; o > 0; o >>= 1) v = fmaxf(v, __shfl_xor_sync(0xFFFFFFFFu, v, o));
    return v;
}

// ---------------- GEMM: C[M,N] = alpha * A[M,K] @ B(,K or K,) (+bias)(+relu) ----------------
// TRANSB=false: B is [K,N] row-major.  TRANSB=true: B is [N,K] row-major (C = A @ B^T).
// All of M,N multiples of 128; K multiple of 16 (true for every call here).
template<bool TRANSB, bool RELU, bool HAS_BIAS>
__global__ __launch_bounds__(256)
void gemm_kernel(const float* __restrict__ A, const float* __restrict__ B,
                 float* __restrict__ C, int M, int N, int K,
                 long long sA, long long sB, long long sC,
                 float alpha, const float* __restrict__ bias)
{
    constexpr int BM = 128, BN = 128, BK = 16, TM = 8, TN = 8;
    __shared__ float As[BK][BM];
    __shared__ float Bs[BK][BN];

    A += (long long)blockIdx.z * sA;
    B += (long long)blockIdx.z * sB;
    C += (long long)blockIdx.z * sC;

    const int tid = threadIdx.x;
    const int tx  = tid & 15;       // 0..15  -> n
    const int ty  = tid >> 4;       // 0..15  -> m
    const int m0  = blockIdx.y * BM;
    const int n0  = blockIdx.x * BN;

    float acc[TM][TN];
    #pragma unroll
    for (int i = 0; i < TM; i++)
        #pragma unroll
        for (int j = 0; j < TN; j++) acc[i][j] = 0.f;

    for (int k0 = 0; k0 < K; k0 += BK) {
        // ---- load A tile (BM x BK), stored transposed As[k][m] ----
        #pragma unroll
        for (int l = 0; l < 2; l++) {
            int idx = tid + l * 256;          // 0..511 float4s
            int r   = idx >> 2;               // row in tile 0..127
            int kq  = (idx & 3) << 2;         // 0,4,8,12
            float4 v = *(const float4*)&A[(size_t)(m0 + r) * K + k0 + kq];
            As[kq + 0][r] = v.x; As[kq + 1][r] = v.y;
            As[kq + 2][r] = v.z; As[kq + 3][r] = v.w;
        }
        // ---- load B tile ----
        if (!TRANSB) {
            #pragma unroll
            for (int l = 0; l < 2; l++) {
                int idx = tid + l * 256;
                int r   = idx >> 5;           // k row 0..15
                int nq  = (idx & 31) << 2;    // 0..124
                *(float4*)&Bs[r][nq] = *(const float4*)&B[(size_t)(k0 + r) * N + n0 + nq];
            }
        } else {
            #pragma unroll
            for (int l = 0; l < 2; l++) {
                int idx = tid + l * 256;
                int r   = idx >> 2;           // n row 0..127
                int kq  = (idx & 3) << 2;
                float4 v = *(const float4*)&B[(size_t)(n0 + r) * K + k0 + kq];
                Bs[kq + 0][r] = v.x; Bs[kq + 1][r] = v.y;
                Bs[kq + 2][r] = v.z; Bs[kq + 3][r] = v.w;
            }
        }
        __syncthreads();

        #pragma unroll
        for (int k = 0; k < BK; k++) {
            float a[TM], b[TN];
            float4 a0 = *(const float4*)&As[k][ty * TM];
            float4 a1 = *(const float4*)&As[k][ty * TM + 4];
            a[0]=a0.x; a[1]=a0.y; a[2]=a0.z; a[3]=a0.w;
            a[4]=a1.x; a[5]=a1.y; a[6]=a1.z; a[7]=a1.w;
            float4 b0 = *(const float4*)&Bs[k][tx * TN];
            float4 b1 = *(const float4*)&Bs[k][tx * TN + 4];
            b[0]=b0.x; b[1]=b0.y; b[2]=b0.z; b[3]=b0.w;
            b[4]=b1.x; b[5]=b1.y; b[6]=b1.z; b[7]=b1.w;
            #pragma unroll
            for (int i = 0; i < TM; i++)
                #pragma unroll
                for (int j = 0; j < TN; j++)
                    acc[i][j] = fmaf(a[i], b[j], acc[i][j]);
        }
        __syncthreads();
    }

    #pragma unroll
    for (int i = 0; i < TM; i++) {
        int m = m0 + ty * TM + i;
        #pragma unroll
        for (int j = 0; j < TN; j += 4) {
            int n = n0 + tx * TN + j;
            float4 v;
            v.x = acc[i][j + 0] * alpha;
            v.y = acc[i][j + 1] * alpha;
            v.z = acc[i][j + 2] * alpha;
            v.w = acc[i][j + 3] * alpha;
            if (HAS_BIAS) {
                v.x += bias[n + 0]; v.y += bias[n + 1];
                v.z += bias[n + 2]; v.w += bias[n + 3];
            }
            if (RELU) {
                v.x = fmaxf(v.x, 0.f); v.y = fmaxf(v.y, 0.f);
                v.z = fmaxf(v.z, 0.f); v.w = fmaxf(v.w, 0.f);
            }
            *(float4*)&C[(size_t)m * N + n] = v;
        }
    }
}

// ---------------- row softmax over scores [B,S,S]; optional causal mask ----------------
template<bool CAUSAL>
__global__ __launch_bounds__(256)
void softmax_kernel(float* __restrict__ S)
{
    __shared__ float red[8];
    const int row = blockIdx.x;           // 0..ROWS-1
    const int b   = row / SEQ;
    const int q   = row - b * SEQ;
    float* p = S + (size_t)b * SEQ * SEQ + (size_t)q * SEQ;
    const int len = CAUSAL ? (q + 1) : SEQ;
    const int tid = threadIdx.x;
    const int lane = tid & 31, wid = tid >> 5;

    // max
    float m = -1e30f;
    for (int j = tid; j < len; j += 256) m = fmaxf(m, p[j]);
    m = warp_max(m);
    if (lane == 0) red[wid] = m;
    __syncthreads();
    m = (lane < 8) ? red[lane] : -1e30f;
    m = warp_max(m);
    m = __shfl_sync(0xFFFFFFFFu, m, 0);

    // exp + sum
    float s = 0.f;
    for (int j = tid; j < len; j += 256) {
        float e = expf(p[j] - m);
        p[j] = e;
        s += e;
    }
    s = warp_sum(s);
    __syncthreads();
    if (lane == 0) red[wid] = s;
    __syncthreads();
    s = (lane < 8) ? red[lane] : 0.f;
    s = warp_sum(s);
    s = __shfl_sync(0xFFFFFFFFu, s, 0);

    const float inv = 1.f / s;
    for (int j = tid; j < len; j += 256) p[j] *= inv;
    if (CAUSAL)
        for (int j = len + tid; j < SEQ; j += 256) p[j] = 0.f;
}

// ---------------- out = LayerNorm(x + r) * gamma + beta, rows of D_MODEL ----------------
__global__ __launch_bounds__(256)
void add_ln_kernel(const float* __restrict__ x, const float* __restrict__ r,
                   const float* __restrict__ gamma, const float* __restrict__ beta,
                   float* __restrict__ out)
{
    __shared__ float red_s[8];
    __shared__ float red_q[8];
    const int row = blockIdx.x;
    const int tid = threadIdx.x;
    const int lane = tid & 31, wid = tid >> 5;
    const size_t base = (size_t)row * D_MODEL;

    float4 vx = *(const float4*)&x[base + tid * 4];
    float4 vr = *(const float4*)&r[base + tid * 4];
    float4 v;
    v.x = vx.x + vr.x; v.y = vx.y + vr.y; v.z = vx.z + vr.z; v.w = vx.w + vr.w;

    float s = v.x + v.y + v.z + v.w;
    float q = v.x * v.x + v.y * v.y + v.z * v.z + v.w * v.w;
    s = warp_sum(s); q = warp_sum(q);
    if (lane == 0) { red_s[wid] = s; red_q[wid] = q; }
    __syncthreads();
    s = (lane < 8) ? red_s[lane] : 0.f;
    q = (lane < 8) ? red_q[lane] : 0.f;
    s = warp_sum(s); q = warp_sum(q);
    s = __shfl_sync(0xFFFFFFFFu, s, 0);
    q = __shfl_sync(0xFFFFFFFFu, q, 0);

    const float mean = s * (1.f / D_MODEL);
    const float var  = q * (1.f / D_MODEL) - mean * mean;
    const float inv  = rsqrtf(var + EPS);

    float4 g = *(const float4*)&gamma[tid * 4];
    float4 be = *(const float4*)&beta[tid * 4];
    float4 o;
    o.x = (v.x - mean) * inv * g.x + be.x;
    o.y = (v.y - mean) * inv * g.y + be.y;
    o.z = (v.z - mean) * inv * g.z + be.z;
    o.w = (v.w - mean) * inv * g.w + be.w;
    *(float4*)&out[base + tid * 4] = o;
}

// ---------------- host-side helpers ----------------
static float* sym(const void* s) {
    void* p = nullptr;
    cudaGetSymbolAddress(&p, s);
    return (float*)p;
}

static void gemm(const float* A, const float* B, float* C, int M, int N, int K,
                 long long sA, long long sB, long long sC, int batch,
                 float alpha, bool transb,
                 const float* bias = nullptr, bool relu = false)
{
    dim3 grid(N / 128, M / 128, batch);
    if (transb) {
        gemm_kernel<true, false, false><<<grid, 256>>>(A, B, C, M, N, K, sA, sB, sC, alpha, nullptr);
    } else if (relu) {
        gemm_kernel<false, true, true><<<grid, 256>>>(A, B, C, M, N, K, sA, sB, sC, alpha, bias);
    } else if (bias) {
        gemm_kernel<false, false, true><<<grid, 256>>>(A, B, C, M, N, K, sA, sB, sC, alpha, bias);
    } else {
        gemm_kernel<false, false, false><<<grid, 256>>>(A, B, C, M, N, K, sA, sB, sC, alpha, nullptr);
    }
}

extern "C" void kernel_launch(void* const* d_in, const int* in_sizes, int n_in,
                              void* d_out, int out_size)
{
    const float* y    = (const float*)d_in[0];
    const float* Z    = (const float*)d_in[1];
    const float* WQ1  = (const float*)d_in[2];
    const float* WK1  = (const float*)d_in[3];
    const float* WV1  = (const float*)d_in[4];
    const float* WQ2  = (const float*)d_in[5];
    const float* WK2  = (const float*)d_in[6];
    const float* WV2  = (const float*)d_in[7];
    const float* Wf1  = (const float*)d_in[8];
    const float* bf1  = (const float*)d_in[9];
    const float* Wf2  = (const float*)d_in[10];
    const float* bf2  = (const float*)d_in[11];
    const float* g1   = (const float*)d_in[12];
    const float* be1  = (const float*)d_in[13];
    const float* g2   = (const float*)d_in[14];
    const float* be2  = (const float*)d_in[15];
    const float* g3   = (const float*)d_in[16];
    const float* be3  = (const float*)d_in[17];
    float* out = (float*)d_out;

    float* Q   = sym(g_Q);
    float* K   = sym(g_K);
    float* V   = sym(g_V);
    float* S   = sym(g_S);
    float* att = sym(g_att);
    float* y1  = sym(g_y1);
    float* y2  = sym(g_y2);
    float* h   = sym(g_h);

    const float scale = 1.f / 32.f;                 // 1/sqrt(1024)
    const long long sQ = (long long)SEQ * D_MODEL;  // per-batch stride in Q/K/V
    const long long sS = (long long)SEQ * SEQ;

    // ---- 1. causal self-attention ----
    gemm(y, WQ1, Q, ROWS, D_MODEL, D_MODEL, 0, 0, 0, 1, 1.f, false);
    gemm(y, WK1, K, ROWS, D_MODEL, D_MODEL, 0, 0, 0, 1, 1.f, false);
    gemm(y, WV1, V, ROWS, D_MODEL, D_MODEL, 0, 0, 0, 1, 1.f, false);
    gemm(Q, K, S, SEQ, SEQ, D_MODEL, sQ, sQ, sS, BATCH, scale, true);       // S = Q K^T / 32
    softmax_kernel<true><<<ROWS, 256>>>(S);
    gemm(S, V, att, SEQ, D_MODEL, SEQ, sS, sQ, sQ, BATCH, 1.f, false);      // att = P V
    add_ln_kernel<<<ROWS, 256>>>(y, att, g1, be1, y1);

    // ---- 2. cross-attention ----
    gemm(y1, WQ2, Q, ROWS, D_MODEL, D_MODEL, 0, 0, 0, 1, 1.f, false);
    gemm(Z,  WK2, K, ROWS, D_MODEL, D_MODEL, 0, 0, 0, 1, 1.f, false);
    gemm(Z,  WV2, V, ROWS, D_MODEL, D_MODEL, 0, 0, 0, 1, 1.f, false);
    gemm(Q, K, S, SEQ, SEQ, D_MODEL, sQ, sQ, sS, BATCH, scale, true);
    softmax_kernel<false><<<ROWS, 256>>>(S);
    gemm(S, V, att, SEQ, D_MODEL, SEQ, sS, sQ, sQ, BATCH, 1.f, false);
    add_ln_kernel<<<ROWS, 256>>>(y1, att, g2, be2, y2);

    // ---- 3. FFN ----
    gemm(y2, Wf1, h, ROWS, D_FF, D_MODEL, 0, 0, 0, 1, 1.f, false, bf1, true);   // relu(y2 Wf1 + b1)
    gemm(h, Wf2, att, ROWS, D_MODEL, D_FF, 0, 0, 0, 1, 1.f, false, bf2, false); // h Wf2 + b2
    add_ln_kernel<<<ROWS, 256>>>(y2, att, g3, be3, out);
}

// round 6
// speedup vs baseline: 2.8729x; 2.8729x over previous
#include <cuda_runtime.h>
#include <cstdint>
#include <math.h>

#define D_MODEL 1024
#define D_FF    4096
#define BATCH   4
#define SEQ     2048
#define ROWS    (BATCH * SEQ)   // 8192
#define EPS     1e-5f

#define NSTAGES 3
#define BM 128
#define BN 128
#define BK 32
#define KPAD (BK + 4)                       // 36 floats = 144B row stride (conflict-free ldmatrix)
#define STAGE_BYTES (BM * KPAD * 4)         // 18432 per operand per stage
#define SMEM_TOTAL (2 * NSTAGES * STAGE_BYTES)

// ---------------- scratch (device globals; no allocations allowed) ----------------
__device__ float g_Q  [(size_t)ROWS * D_MODEL];
__device__ float g_K  [(size_t)ROWS * D_MODEL];
__device__ float g_V  [(size_t)ROWS * D_MODEL];
__device__ float g_Vt [(size_t)ROWS * D_MODEL];
__device__ float g_S  [(size_t)BATCH * SEQ * SEQ];
__device__ float g_att[(size_t)ROWS * D_MODEL];
__device__ float g_y1 [(size_t)ROWS * D_MODEL];
__device__ float g_y2 [(size_t)ROWS * D_MODEL];
__device__ float g_h  [(size_t)ROWS * D_FF];
__device__ float g_Bt [(size_t)D_FF * D_MODEL];

// ---------------- PTX helpers (all plain-sm_103-legal: cp.async / ldmatrix / mma.sync) ----------
__device__ __forceinline__ uint32_t smem_u32(const void* p) {
    uint32_t a;
    asm("{ .reg .u64 t; cvta.to.shared.u64 t, %1; cvt.u32.u64 %0, t; }" : "=r"(a) : "l"(p));
    return a;
}
__device__ __forceinline__ void cp_async16(uint32_t dst, const void* src) {
    asm volatile("cp.async.cg.shared.global [%0], [%1], 16;" :: "r"(dst), "l"(src) : "memory");
}
#define CP_COMMIT() asm volatile("cp.async.commit_group;" ::: "memory")
#define CP_WAIT(n)  asm volatile("cp.async.wait_group %0;" :: "n"(n) : "memory")

#define LDMX4(r0, r1, r2, r3, addr) \
    asm volatile("ldmatrix.sync.aligned.m8n8.x4.shared.b16 {%0,%1,%2,%3}, [%4];" \
                 : "=r"(r0), "=r"(r1), "=r"(r2), "=r"(r3) : "r"(addr))

#define CVT_TF32(x) asm("cvt.rna.tf32.f32 %0, %0;" : "+r"(x))

#define MMA_TF32(d, a0, a1, a2, a3, b0, b1) \
    asm volatile("mma.sync.aligned.m16n8k8.row.col.f32.tf32.tf32.f32 " \
                 "{%0,%1,%2,%3}, {%4,%5,%6,%7}, {%8,%9}, {%0,%1,%2,%3};" \
                 : "+f"((d)[0]), "+f"((d)[1]), "+f"((d)[2]), "+f"((d)[3]) \
                 : "r"(a0), "r"(a1), "r"(a2), "r"(a3), "r"(b0), "r"(b1))

// ---------------- tf32 tensor-core GEMM: C[M,N] = alpha*A[M,K]@B[N,K]^T (+bias)(+relu) ----------
// A: [M,K] row-major. B: [N,K] row-major. M,N mult of 128, K mult of 32.
__global__ __launch_bounds__(256, 1)
void gemm_tc(const float* __restrict__ A, const float* __restrict__ B,
             float* __restrict__ C, int M, int N, int K,
             long long sA, long long sB, long long sC,
             float alpha, const float* __restrict__ bias, int relu)
{
    extern __shared__ char smem[];
    const int tid  = threadIdx.x;
    const int wid  = tid >> 5;
    const int lane = tid & 31;

    A += (long long)blockIdx.z * sA;
    B += (long long)blockIdx.z * sB;
    C += (long long)blockIdx.z * sC;
    const int m0 = blockIdx.y * BM;
    const int n0 = blockIdx.x * BN;

    const uint32_t sA0 = smem_u32(smem);
    const uint32_t sB0 = sA0 + NSTAGES * STAGE_BYTES;

    const int wm = (wid & 3) * 32;     // warp M offset (2 m16-tiles)
    const int wn = (wid >> 2) * 64;    // warp N offset (8 n8-tiles)

    float acc[2][8][4];
    #pragma unroll
    for (int i = 0; i < 2; i++)
        #pragma unroll
        for (int j = 0; j < 8; j++)
            #pragma unroll
            for (int k = 0; k < 4; k++) acc[i][j][k] = 0.f;

    const int nch = K >> 5;

    // global -> smem stage loader (rows padded to KPAD floats; 16B-aligned chunks)
    auto load_chunk = [&](int c, int s) {
        const float* Ab = A + (size_t)m0 * K + c * BK;
        const float* Bb = B + (size_t)n0 * K + c * BK;
        const uint32_t as = sA0 + s * STAGE_BYTES;
        const uint32_t bs = sB0 + s * STAGE_BYTES;
        #pragma unroll
        for (int i = 0; i < 4; i++) {
            int idx = tid + i * 256;          // 0..1023
            int r   = idx >> 3;               // 0..127
            int q   = idx & 7;                // float4 within 32-float row
            uint32_t d = (uint32_t)(r * (KPAD * 4) + q * 16);
            cp_async16(as + d, Ab + (size_t)r * K + q * 4);
            cp_async16(bs + d, Bb + (size_t)r * K + q * 4);
        }
        CP_COMMIT();
    };

    #pragma unroll
    for (int s = 0; s < NSTAGES - 1; s++) load_chunk(s, s);

    // per-lane ldmatrix base offsets (bytes, within a stage)
    const uint32_t aOff = (uint32_t)(((wm + (lane & 15)) * KPAD + (lane >> 4) * 4) * 4);
    const uint32_t bOff = (uint32_t)(((wn + (lane >> 4) * 8 + (lane & 7)) * KPAD
                                      + ((lane >> 3) & 1) * 4) * 4);

    for (int c = 0; c < nch; c++) {
        CP_WAIT(NSTAGES - 2);
        __syncthreads();
        if (c + NSTAGES - 1 < nch) load_chunk(c + NSTAGES - 1, (c + NSTAGES - 1) % NSTAGES);

        const int s = c % NSTAGES;
        const uint32_t aBase = sA0 + s * STAGE_BYTES + aOff;
        const uint32_t bBase = sB0 + s * STAGE_BYTES + bOff;

        #pragma unroll
        for (int ks = 0; ks < 4; ks++) {
            uint32_t a[2][4], b[4][4];
            #pragma unroll
            for (int mt = 0; mt < 2; mt++) {
                LDMX4(a[mt][0], a[mt][1], a[mt][2], a[mt][3],
                      aBase + mt * (16 * KPAD * 4) + ks * 32);
                CVT_TF32(a[mt][0]); CVT_TF32(a[mt][1]);
                CVT_TF32(a[mt][2]); CVT_TF32(a[mt][3]);
            }
            #pragma unroll
            for (int np = 0; np < 4; np++) {
                LDMX4(b[np][0], b[np][1], b[np][2], b[np][3],
                      bBase + np * (16 * KPAD * 4) + ks * 32);
                CVT_TF32(b[np][0]); CVT_TF32(b[np][1]);
                CVT_TF32(b[np][2]); CVT_TF32(b[np][3]);
            }
            #pragma unroll
            for (int mt = 0; mt < 2; mt++)
                #pragma unroll
                for (int np = 0; np < 4; np++) {
                    MMA_TF32(acc[mt][2 * np + 0], a[mt][0], a[mt][1], a[mt][2], a[mt][3],
                             b[np][0], b[np][1]);
                    MMA_TF32(acc[mt][2 * np + 1], a[mt][0], a[mt][1], a[mt][2], a[mt][3],
                             b[np][2], b[np][3]);
                }
        }
    }

    // ---- epilogue: c-fragment rows L>>2 and (L>>2)+8, cols (L&3)*2 ----
    #pragma unroll
    for (int mt = 0; mt < 2; mt++) {
        #pragma unroll
        for (int nt = 0; nt < 8; nt++) {
            const int row = m0 + wm + mt * 16 + (lane >> 2);
            const int col = n0 + wn + nt * 8 + (lane & 3) * 2;
            float2 v0, v1;
            v0.x = acc[mt][nt][0] * alpha; v0.y = acc[mt][nt][1] * alpha;
            v1.x = acc[mt][nt][2] * alpha; v1.y = acc[mt][nt][3] * alpha;
            if (bias) {
                float b0 = __ldg(bias + col), b1 = __ldg(bias + col + 1);
                v0.x += b0; v0.y += b1; v1.x += b0; v1.y += b1;
            }
            if (relu) {
                v0.x = fmaxf(v0.x, 0.f); v0.y = fmaxf(v0.y, 0.f);
                v1.x = fmaxf(v1.x, 0.f); v1.y = fmaxf(v1.y, 0.f);
            }
            *(float2*)&C[(size_t)row * N + col]       = v0;
            *(float2*)&C[(size_t)(row + 8) * N + col] = v1;
        }
    }
}

// ---------------- transpose: out[C,R] = in[R,C]^T (batched) ----------------
__global__ __launch_bounds__(256)
void transpose_kernel(const float* __restrict__ in, float* __restrict__ out,
                      int R, int C, long long sIn, long long sOut)
{
    __shared__ float t[32][33];
    in  += (long long)blockIdx.z * sIn;
    out += (long long)blockIdx.z * sOut;
    const int c0 = blockIdx.x * 32, r0 = blockIdx.y * 32;
    const int x = threadIdx.x, y = threadIdx.y;   // 32 x 8
    #pragma unroll
    for (int i = 0; i < 32; i += 8)
        t[y + i][x] = in[(size_t)(r0 + y + i) * C + c0 + x];
    __syncthreads();
    #pragma unroll
    for (int i = 0; i < 32; i += 8)
        out[(size_t)(c0 + y + i) * R + r0 + x] = t[x][y + i];
}

// ---------------- reductions ----------------
__device__ __forceinline__ float warp_sum(float v) {
    #pragma unroll
    for (int o = 16; o > 0; o >>= 1) v += __shfl_xor_sync(0xFFFFFFFFu, v, o);
    return v;
}
__device__ __forceinline__ float warp_max(float v) {
    #pragma unroll
    for (int o = 16; o > 0; o >>= 1) v = fmaxf(v, __shfl_xor_sync(0xFFFFFFFFu, v, o));
    return v;
}

// ---------------- row softmax over scores [B,S,S]; optional causal mask ----------------
template<bool CAUSAL>
__global__ __launch_bounds__(256)
void softmax_kernel(float* __restrict__ S)
{
    __shared__ float red[8];
    const int row = blockIdx.x;
    const int b   = row / SEQ;
    const int q   = row - b * SEQ;
    float* p = S + (size_t)b * SEQ * SEQ + (size_t)q * SEQ;
    const int len = CAUSAL ? (q + 1) : SEQ;
    const int tid = threadIdx.x;
    const int lane = tid & 31, wid = tid >> 5;

    float m = -1e30f;
    for (int j = tid; j < len; j += 256) m = fmaxf(m, p[j]);
    m = warp_max(m);
    if (lane == 0) red[wid] = m;
    __syncthreads();
    m = (lane < 8) ? red[lane] : -1e30f;
    m = warp_max(m);
    m = __shfl_sync(0xFFFFFFFFu, m, 0);

    float s = 0.f;
    for (int j = tid; j < len; j += 256) {
        float e = expf(p[j] - m);
        p[j] = e;
        s += e;
    }
    s = warp_sum(s);
    __syncthreads();
    if (lane == 0) red[wid] = s;
    __syncthreads();
    s = (lane < 8) ? red[lane] : 0.f;
    s = warp_sum(s);
    s = __shfl_sync(0xFFFFFFFFu, s, 0);

    const float inv = 1.f / s;
    for (int j = tid; j < len; j += 256) p[j] *= inv;
    if (CAUSAL)
        for (int j = len + tid; j < SEQ; j += 256) p[j] = 0.f;
}

// ---------------- out = LayerNorm(x + r) * gamma + beta ----------------
__global__ __launch_bounds__(256)
void add_ln_kernel(const float* __restrict__ x, const float* __restrict__ r,
                   const float* __restrict__ gamma, const float* __restrict__ beta,
                   float* __restrict__ out)
{
    __shared__ float red_s[8];
    __shared__ float red_q[8];
    const int row = blockIdx.x;
    const int tid = threadIdx.x;
    const int lane = tid & 31, wid = tid >> 5;
    const size_t base = (size_t)row * D_MODEL;

    float4 vx = *(const float4*)&x[base + tid * 4];
    float4 vr = *(const float4*)&r[base + tid * 4];
    float4 v;
    v.x = vx.x + vr.x; v.y = vx.y + vr.y; v.z = vx.z + vr.z; v.w = vx.w + vr.w;

    float s = v.x + v.y + v.z + v.w;
    float q = v.x * v.x + v.y * v.y + v.z * v.z + v.w * v.w;
    s = warp_sum(s); q = warp_sum(q);
    if (lane == 0) { red_s[wid] = s; red_q[wid] = q; }
    __syncthreads();
    s = (lane < 8) ? red_s[lane] : 0.f;
    q = (lane < 8) ? red_q[lane] : 0.f;
    s = warp_sum(s); q = warp_sum(q);
    s = __shfl_sync(0xFFFFFFFFu, s, 0);
    q = __shfl_sync(0xFFFFFFFFu, q, 0);

    const float mean = s * (1.f / D_MODEL);
    const float var  = q * (1.f / D_MODEL) - mean * mean;
    const float inv  = rsqrtf(var + EPS);

    float4 g  = *(const float4*)&gamma[tid * 4];
    float4 be = *(const float4*)&beta[tid * 4];
    float4 o;
    o.x = (v.x - mean) * inv * g.x + be.x;
    o.y = (v.y - mean) * inv * g.y + be.y;
    o.z = (v.z - mean) * inv * g.z + be.z;
    o.w = (v.w - mean) * inv * g.w + be.w;
    *(float4*)&out[base + tid * 4] = o;
}

// ---------------- host-side helpers ----------------
static float* sym(const void* s) {
    void* p = nullptr;
    cudaGetSymbolAddress(&p, s);
    return (float*)p;
}

static void launch_gemm(const float* A, const float* B, float* C,
                        int M, int N, int K,
                        long long sA, long long sB, long long sC, int batch,
                        float alpha, const float* bias, int relu)
{
    cudaFuncSetAttribute(gemm_tc, cudaFuncAttributeMaxDynamicSharedMemorySize, SMEM_TOTAL);
    dim3 grid(N / BN, M / BM, batch);
    gemm_tc<<<grid, 256, SMEM_TOTAL>>>(A, B, C, M, N, K, sA, sB, sC, alpha, bias, relu);
}

static void launch_transpose(const float* in, float* out, int R, int C,
                             long long sIn, long long sOut, int batch)
{
    dim3 grid(C / 32, R / 32, batch);
    transpose_kernel<<<grid, dim3(32, 8)>>>(in, out, R, C, sIn, sOut);
}

extern "C" void kernel_launch(void* const* d_in, const int* in_sizes, int n_in,
                              void* d_out, int out_size)
{
    const float* y    = (const float*)d_in[0];
    const float* Z    = (const float*)d_in[1];
    const float* WQ1  = (const float*)d_in[2];
    const float* WK1  = (const float*)d_in[3];
    const float* WV1  = (const float*)d_in[4];
    const float* WQ2  = (const float*)d_in[5];
    const float* WK2  = (const float*)d_in[6];
    const float* WV2  = (const float*)d_in[7];
    const float* Wf1  = (const float*)d_in[8];
    const float* bf1  = (const float*)d_in[9];
    const float* Wf2  = (const float*)d_in[10];
    const float* bf2  = (const float*)d_in[11];
    const float* g1   = (const float*)d_in[12];
    const float* be1  = (const float*)d_in[13];
    const float* g2   = (const float*)d_in[14];
    const float* be2  = (const float*)d_in[15];
    const float* g3   = (const float*)d_in[16];
    const float* be3  = (const float*)d_in[17];
    float* out = (float*)d_out;

    float* Q   = sym(g_Q);
    float* K   = sym(g_K);
    float* V   = sym(g_V);
    float* Vt  = sym(g_Vt);
    float* S   = sym(g_S);
    float* att = sym(g_att);
    float* y1  = sym(g_y1);
    float* y2  = sym(g_y2);
    float* h   = sym(g_h);
    float* Bt  = sym(g_Bt);

    const float scale = 1.f / 32.f;                 // 1/sqrt(1024)
    const long long sQ = (long long)SEQ * D_MODEL;  // per-batch stride
    const long long sS = (long long)SEQ * SEQ;

    // ---- 1. causal self-attention ----
    launch_transpose(WQ1, Bt, D_MODEL, D_MODEL, 0, 0, 1);
    launch_gemm(y, Bt, Q, ROWS, D_MODEL, D_MODEL, 0, 0, 0, 1, 1.f, nullptr, 0);
    launch_transpose(WK1, Bt, D_MODEL, D_MODEL, 0, 0, 1);
    launch_gemm(y, Bt, K, ROWS, D_MODEL, D_MODEL, 0, 0, 0, 1, 1.f, nullptr, 0);
    launch_transpose(WV1, Bt, D_MODEL, D_MODEL, 0, 0, 1);
    launch_gemm(y, Bt, V, ROWS, D_MODEL, D_MODEL, 0, 0, 0, 1, 1.f, nullptr, 0);

    launch_gemm(Q, K, S, SEQ, SEQ, D_MODEL, sQ, sQ, sS, BATCH, scale, nullptr, 0);  // S = QK^T/32
    softmax_kernel<true><<<ROWS, 256>>>(S);
    launch_transpose(V, Vt, SEQ, D_MODEL, sQ, sQ, BATCH);                            // Vt[b] = V[b]^T
    launch_gemm(S, Vt, att, SEQ, D_MODEL, SEQ, sS, sQ, sQ, BATCH, 1.f, nullptr, 0);  // att = P V
    add_ln_kernel<<<ROWS, 256>>>(y, att, g1, be1, y1);

    // ---- 2. cross-attention ----
    launch_transpose(WQ2, Bt, D_MODEL, D_MODEL, 0, 0, 1);
    launch_gemm(y1, Bt, Q, ROWS, D_MODEL, D_MODEL, 0, 0, 0, 1, 1.f, nullptr, 0);
    launch_transpose(WK2, Bt, D_MODEL, D_MODEL, 0, 0, 1);
    launch_gemm(Z,  Bt, K, ROWS, D_MODEL, D_MODEL, 0, 0, 0, 1, 1.f, nullptr, 0);
    launch_transpose(WV2, Bt, D_MODEL, D_MODEL, 0, 0, 1);
    launch_gemm(Z,  Bt, V, ROWS, D_MODEL, D_MODEL, 0, 0, 0, 1, 1.f, nullptr, 0);

    launch_gemm(Q, K, S, SEQ, SEQ, D_MODEL, sQ, sQ, sS, BATCH, scale, nullptr, 0);
    softmax_kernel<false><<<ROWS, 256>>>(S);
    launch_transpose(V, Vt, SEQ, D_MODEL, sQ, sQ, BATCH);
    launch_gemm(S, Vt, att, SEQ, D_MODEL, SEQ, sS, sQ, sQ, BATCH, 1.f, nullptr, 0);
    add_ln_kernel<<<ROWS, 256>>>(y1, att, g2, be2, y2);

    // ---- 3. FFN ----
    launch_transpose(Wf1, Bt, D_MODEL, D_FF, 0, 0, 1);                               // [4096,1024]
    launch_gemm(y2, Bt, h, ROWS, D_FF, D_MODEL, 0, 0, 0, 1, 1.f, bf1, 1);            // relu(y2 Wf1 + b1)
    launch_transpose(Wf2, Bt, D_FF, D_MODEL, 0, 0, 1);                               // [1024,4096]
    launch_gemm(h, Bt, att, ROWS, D_MODEL, D_FF, 0, 0, 0, 1, 1.f, bf2, 0);           // h Wf2 + b2
    add_ln_kernel<<<ROWS, 256>>>(y2, att, g3, be3, out);
}